// round 3
// baseline (speedup 1.0000x reference)
#include <cuda_runtime.h>
#include <math_constants.h>

#define C        32000
#define GRID_PTS 100
#define NMIDS    (GRID_PTS - 1)
#define THREADS  1024
#define NWARP    (THREADS / 32)
#define C4       (C / 4)           // 8000 float4 per row

// smem layout (floats): xbuf[C] | mids_s[NMIDS] | ybuf[GRID_PTS] | red[NWARP+1]
#define SMEM_FLOATS (C + NMIDS + GRID_PTS + NWARP + 1)
#define SMEM_BYTES  (SMEM_FLOATS * sizeof(float))

__global__ __launch_bounds__(THREADS, 1)
void calib_kernel(const float* __restrict__ logits,
                  const float* __restrict__ log_temp,
                  const float* __restrict__ iso_x,
                  const float* __restrict__ iso_y,
                  float* __restrict__ out)
{
    extern __shared__ float smem[];
    float* xbuf   = smem;                    // C
    float* mids_s = xbuf + C;                // NMIDS  (midpoints * S)
    float* ybuf   = mids_s + NMIDS;          // GRID_PTS
    float* red    = ybuf + GRID_PTS;         // NWARP + 1

    const int tid  = threadIdx.x;
    const int lane = tid & 31;
    const int wid  = tid >> 5;
    const long long row = blockIdx.x;

    // temperature = clamp(exp(log_T), 0.1, 10); fold log2(e)/T into the scale
    const float T  = fminf(fmaxf(expf(log_temp[0]), 0.1f), 10.0f);
    const float s2 = 1.4426950408889634f / T;   // base-2 scale

    // y table -> smem (doesn't depend on S)
    if (tid < GRID_PTS) ybuf[tid] = iso_y[tid];

    const float4* lg4 = reinterpret_cast<const float4*>(logits + row * (long long)C);
    float4*       x4  = reinterpret_cast<float4*>(xbuf);

    // ---- Phase 1: single HBM read; scale; stage to smem; online max ----
    float m = -CUDART_INF_F;
    #pragma unroll 2
    for (int i = tid; i < C4; i += THREADS) {
        float4 v = lg4[i];
        v.x *= s2; v.y *= s2; v.z *= s2; v.w *= s2;
        x4[i] = v;
        m = fmaxf(m, fmaxf(fmaxf(v.x, v.y), fmaxf(v.z, v.w)));
    }
    #pragma unroll
    for (int o = 16; o; o >>= 1) m = fmaxf(m, __shfl_xor_sync(0xffffffffu, m, o));
    if (lane == 0) red[wid] = m;
    __syncthreads();
    if (wid == 0) {
        float mm = (lane < NWARP) ? red[lane] : -CUDART_INF_F;
        #pragma unroll
        for (int o = 16; o; o >>= 1) mm = fmaxf(mm, __shfl_xor_sync(0xffffffffu, mm, o));
        if (lane == 0) red[NWARP] = mm;
    }
    __syncthreads();
    const float M = red[NWARP];
    __syncthreads();   // everyone has M before red[] is reused

    // ---- Phase 2: e = 2^(x - M) in place; block sum ----
    float s = 0.0f;
    #pragma unroll 2
    for (int i = tid; i < C4; i += THREADS) {
        float4 v = x4[i];
        v.x = exp2f(v.x - M);
        v.y = exp2f(v.y - M);
        v.z = exp2f(v.z - M);
        v.w = exp2f(v.w - M);
        x4[i] = v;
        s += (v.x + v.y) + (v.z + v.w);
    }
    #pragma unroll
    for (int o = 16; o; o >>= 1) s += __shfl_xor_sync(0xffffffffu, s, o);
    if (lane == 0) red[wid] = s;
    __syncthreads();
    if (wid == 0) {
        float ss = (lane < NWARP) ? red[lane] : 0.0f;
        #pragma unroll
        for (int o = 16; o; o >>= 1) ss += __shfl_xor_sync(0xffffffffu, ss, o);
        if (lane == 0) red[NWARP] = ss;
    }
    __syncthreads();
    const float S = red[NWARP];

    // pre-scale midpoints by S: searchsorted(mids, e/S) == count(mids[i]*S < e)
    if (tid < NMIDS) mids_s[tid] = 0.5f * (iso_x[tid] + iso_x[tid + 1]) * S;
    __syncthreads();

    const float m0 = mids_s[0];
    const float y0 = ybuf[0];
    float4* out4 = reinterpret_cast<float4*>(out + row * (long long)C);

    // ---- Phase 3: index lookup + single HBM write ----
    #pragma unroll 2
    for (int i = tid; i < C4; i += THREADS) {
        float4 e = x4[i];
        float4 r;
        float* ep = &e.x;
        float* rp = &r.x;
        #pragma unroll
        for (int k = 0; k < 4; k++) {
            float ev = ep[k];
            if (ev <= m0) {
                // fast path: p <= mids[0] -> idx 0 (covers ~all of a softmax row)
                rp[k] = y0;
            } else {
                // count of mids_s < ev over [0, NMIDS)
                int lo = 1, hi = NMIDS;          // mids_s[0] < ev already known
                while (lo < hi) {
                    int mid = (lo + hi) >> 1;
                    if (mids_s[mid] < ev) lo = mid + 1; else hi = mid;
                }
                rp[k] = ybuf[lo];
            }
        }
        out4[i] = r;
    }
}

extern "C" void kernel_launch(void* const* d_in, const int* in_sizes, int n_in,
                              void* d_out, int out_size) {
    const float* logits   = (const float*)d_in[0];
    const float* log_temp = (const float*)d_in[1];
    const float* iso_x    = (const float*)d_in[2];
    const float* iso_y    = (const float*)d_in[3];
    float* out = (float*)d_out;

    const int rows = out_size / C;

    cudaFuncSetAttribute(calib_kernel,
                         cudaFuncAttributeMaxDynamicSharedMemorySize,
                         (int)SMEM_BYTES);
    calib_kernel<<<rows, THREADS, SMEM_BYTES>>>(logits, log_temp, iso_x, iso_y, out);
}